// round 5
// baseline (speedup 1.0000x reference)
#include <cuda_runtime.h>
#include <cuda_bf16.h>
#include <math.h>

// Problem constants
#define B_   32
#define T_   128
#define H_   768
#define IN_  256
#define H2_  1536

// exp(-1/20)
#define ALPHA_   0.951229424500714f
#define OMA_     0.048770575499286f
#define DTR_     0.951229424500714f
#define OMD_     0.048770575499286f
#define ETA_     0.1f
#define CIKV_    0.02f

// Output offsets (floats): mem | keys | vals
#define OUT_MEM_   0
#define OUT_KEYS_  18874368
#define OUT_VALS_  22020096

// Scratch
__device__ float g_i[B_ * T_ * H2_];
__device__ float g_key[B_ * T_ * H_];
__device__ float g_ktr[B_ * T_ * H_];
__device__ float g_vtr[B_ * T_ * H_];
__device__ float g_Apart[6 * B_ * T_ * T_];

__device__ __forceinline__ float tanh_fast(float x) {
    float y;
    asm("tanh.approx.f32 %0, %1;" : "=f"(y) : "f"(x));
    return y;
}

// ---------------------------------------------------------------------------
// mma.sync helpers (bf16 hi/lo split GEMM)
// ---------------------------------------------------------------------------
__device__ __forceinline__ void ldsm_x4(unsigned addr, unsigned& r0, unsigned& r1,
                                        unsigned& r2, unsigned& r3) {
    asm volatile("ldmatrix.sync.aligned.m8n8.x4.shared.b16 {%0,%1,%2,%3}, [%4];"
                 : "=r"(r0), "=r"(r1), "=r"(r2), "=r"(r3) : "r"(addr));
}
__device__ __forceinline__ void ldsm_x4t(unsigned addr, unsigned& r0, unsigned& r1,
                                         unsigned& r2, unsigned& r3) {
    asm volatile("ldmatrix.sync.aligned.m8n8.x4.trans.shared.b16 {%0,%1,%2,%3}, [%4];"
                 : "=r"(r0), "=r"(r1), "=r"(r2), "=r"(r3) : "r"(addr));
}
__device__ __forceinline__ void mma16816(float* c, unsigned a0, unsigned a1,
                                         unsigned a2, unsigned a3,
                                         unsigned b0, unsigned b1) {
    asm volatile(
        "mma.sync.aligned.m16n8k16.row.col.f32.bf16.bf16.f32 "
        "{%0,%1,%2,%3}, {%4,%5,%6,%7}, {%8,%9}, {%0,%1,%2,%3};"
        : "+f"(c[0]), "+f"(c[1]), "+f"(c[2]), "+f"(c[3])
        : "r"(a0), "r"(a1), "r"(a2), "r"(a3), "r"(b0), "r"(b1));
}
__device__ __forceinline__ void split_bf16(float v, __nv_bfloat16& hi, __nv_bfloat16& lo) {
    hi = __float2bfloat16(v);
    lo = __float2bfloat16(v - __bfloat162float(hi));
}

#define SRM 40    // smem stride (halves) row-major [m][k] tiles (128x32)
#define SKM 136   // smem stride (halves) k-major [k][m] tiles (32x128)
#define RM_BUF_HALVES (128 * SRM)          // 5120
#define RM_BUF_BYTES  (RM_BUF_HALVES * 2)  // 10240
#define KM_BUF_HALVES (32 * SKM)           // 4352
#define KM_BUF_BYTES  (KM_BUF_HALVES * 2)  // 8704

// One BK=32 compute step: row-major smem tiles [128][SRM], no-trans ldmatrix.
__device__ __forceinline__ void mma_step_rm(
    unsigned bAh, unsigned bAl, unsigned bBh, unsigned bBl,
    int wm, int wn, int lane, float acc[4][4][4])
{
    const int lr = lane & 15;
    const int kh = (lane >> 4) * 8;
#pragma unroll
    for (int ks = 0; ks < 32; ks += 16) {
        unsigned ah[4][4], al[4][4], bh[4][2], bl[4][2];
#pragma unroll
        for (int i = 0; i < 4; i++) {
            unsigned off = 2u * ((wm * 64 + i * 16 + lr) * SRM + ks + kh);
            ldsm_x4(bAh + off, ah[i][0], ah[i][1], ah[i][2], ah[i][3]);
            ldsm_x4(bAl + off, al[i][0], al[i][1], al[i][2], al[i][3]);
        }
#pragma unroll
        for (int p = 0; p < 2; p++) {
            unsigned off = 2u * ((wn * 32 + p * 16 + lr) * SRM + ks + kh);
            unsigned r0, r1, r2, r3;
            ldsm_x4(bBh + off, r0, r1, r2, r3);
            bh[p * 2 + 0][0] = r0; bh[p * 2 + 0][1] = r2;
            bh[p * 2 + 1][0] = r1; bh[p * 2 + 1][1] = r3;
            ldsm_x4(bBl + off, r0, r1, r2, r3);
            bl[p * 2 + 0][0] = r0; bl[p * 2 + 0][1] = r2;
            bl[p * 2 + 1][0] = r1; bl[p * 2 + 1][1] = r3;
        }
#pragma unroll
        for (int i = 0; i < 4; i++)
#pragma unroll
            for (int j = 0; j < 4; j++) {
                mma16816(acc[i][j], ah[i][0], ah[i][1], ah[i][2], ah[i][3],
                         bh[j][0], bh[j][1]);
                mma16816(acc[i][j], ah[i][0], ah[i][1], ah[i][2], ah[i][3],
                         bl[j][0], bl[j][1]);
                mma16816(acc[i][j], al[i][0], al[i][1], al[i][2], al[i][3],
                         bh[j][0], bh[j][1]);
            }
    }
}

// One BK=32 compute step: k-major smem tiles [32][SKM], trans ldmatrix.
__device__ __forceinline__ void mma_step_km(
    unsigned bAh, unsigned bAl, unsigned bBh, unsigned bBl,
    int wm, int wn, int lane, float acc[4][4][4])
{
    const int krow = (lane & 7) + ((lane >> 4) << 3);
    const int mcol = ((lane >> 3) & 1) * 8;
#pragma unroll
    for (int ks = 0; ks < 32; ks += 16) {
        unsigned ah[4][4], al[4][4], bh[4][2], bl[4][2];
#pragma unroll
        for (int i = 0; i < 4; i++) {
            unsigned off = 2u * ((ks + krow) * SKM + wm * 64 + i * 16 + mcol);
            ldsm_x4t(bAh + off, ah[i][0], ah[i][1], ah[i][2], ah[i][3]);
            ldsm_x4t(bAl + off, al[i][0], al[i][1], al[i][2], al[i][3]);
        }
#pragma unroll
        for (int p = 0; p < 2; p++) {
            unsigned off = 2u * ((ks + krow) * SKM + wn * 32 + p * 16 + mcol);
            unsigned r0, r1, r2, r3;
            ldsm_x4t(bBh + off, r0, r1, r2, r3);
            bh[p * 2 + 0][0] = r0; bh[p * 2 + 0][1] = r2;
            bh[p * 2 + 1][0] = r1; bh[p * 2 + 1][1] = r3;
            ldsm_x4t(bBl + off, r0, r1, r2, r3);
            bl[p * 2 + 0][0] = r0; bl[p * 2 + 0][1] = r2;
            bl[p * 2 + 1][0] = r1; bl[p * 2 + 1][1] = r3;
        }
#pragma unroll
        for (int i = 0; i < 4; i++)
#pragma unroll
            for (int j = 0; j < 4; j++) {
                mma16816(acc[i][j], ah[i][0], ah[i][1], ah[i][2], ah[i][3],
                         bh[j][0], bh[j][1]);
                mma16816(acc[i][j], ah[i][0], ah[i][1], ah[i][2], ah[i][3],
                         bl[j][0], bl[j][1]);
                mma16816(acc[i][j], al[i][0], al[i][1], al[i][2], al[i][3],
                         bh[j][0], bh[j][1]);
            }
    }
}

// --- register prefetch loaders + split/store ---
__device__ __forceinline__ void ldg_rm(const float* __restrict__ src, int ld,
                                       int tid, float4 r[4]) {
#pragma unroll
    for (int l = 0; l < 4; l++) {
        int idx = tid + l * 256;
        int row = idx >> 3;
        int c4  = idx & 7;
        r[l] = *(const float4*)&src[row * ld + c4 * 4];
    }
}
__device__ __forceinline__ void sts_rm(const float4 r[4],
                                       __nv_bfloat16* sh, __nv_bfloat16* sl,
                                       int tid) {
#pragma unroll
    for (int l = 0; l < 4; l++) {
        int idx = tid + l * 256;
        int row = idx >> 3;
        int c4  = idx & 7;
        __nv_bfloat16 h0, l0, h1, l1, h2, l2, h3, l3;
        split_bf16(r[l].x, h0, l0); split_bf16(r[l].y, h1, l1);
        split_bf16(r[l].z, h2, l2); split_bf16(r[l].w, h3, l3);
        int o = row * SRM + c4 * 4;
        sh[o + 0] = h0; sh[o + 1] = h1; sh[o + 2] = h2; sh[o + 3] = h3;
        sl[o + 0] = l0; sl[o + 1] = l1; sl[o + 2] = l2; sl[o + 3] = l3;
    }
}
__device__ __forceinline__ void ldg_km(const float* __restrict__ src, int ld,
                                       int tid, float4 r[4]) {
#pragma unroll
    for (int l = 0; l < 4; l++) {
        int idx = tid + l * 256;
        int s = idx >> 5;
        int q = idx & 31;
        r[l] = *(const float4*)&src[s * ld + q * 4];
    }
}
__device__ __forceinline__ void sts_km(const float4 r[4],
                                       __nv_bfloat16* sh, __nv_bfloat16* sl,
                                       int tid) {
#pragma unroll
    for (int l = 0; l < 4; l++) {
        int idx = tid + l * 256;
        int s = idx >> 5;
        int q = idx & 31;
        __nv_bfloat16 h0, l0, h1, l1, h2, l2, h3, l3;
        split_bf16(r[l].x, h0, l0); split_bf16(r[l].y, h1, l1);
        split_bf16(r[l].z, h2, l2); split_bf16(r[l].w, h3, l3);
        int o = s * SKM + q * 4;
        sh[o + 0] = h0; sh[o + 1] = h1; sh[o + 2] = h2; sh[o + 3] = h3;
        sl[o + 0] = l0; sl[o + 1] = l1; sl[o + 2] = l2; sl[o + 3] = l3;
    }
}

// Epilogue: write 4x4 m16n8 tiles to gmem, scaled.
__device__ __forceinline__ void epilogue(float* dst, int ldc, float scale,
                                         int wm, int wn, int lane,
                                         float acc[4][4][4])
{
    const int r0 = lane >> 2;
    const int c0 = (lane & 3) * 2;
#pragma unroll
    for (int i = 0; i < 4; i++)
#pragma unroll
        for (int j = 0; j < 4; j++) {
            int row = wm * 64 + i * 16 + r0;
            int col = wn * 32 + j * 8 + c0;
            float2 v0 = make_float2(scale * acc[i][j][0], scale * acc[i][j][1]);
            float2 v1 = make_float2(scale * acc[i][j][2], scale * acc[i][j][3]);
            *(float2*)&dst[row * ldc + col] = v0;
            *(float2*)&dst[(row + 8) * ldc + col] = v1;
        }
}

// ---------------------------------------------------------------------------
// K1: g_i[m][n] = sum_k x[m][k] * W[n][k]   M=4096 N=1536 K=256 (NK=8)
//     2-stage smem pipeline, register prefetch, 1 sync/iter.
//     Dyn smem: 8 bufs x 10240B = 80KB.
// ---------------------------------------------------------------------------
__global__ __launch_bounds__(256) void k1_gemm_in(
    const float* __restrict__ x, const float* __restrict__ W)
{
    extern __shared__ __nv_bfloat16 dyn1[];
    const int m0 = blockIdx.y * 128;
    const int n0 = blockIdx.x * 128;
    const int tid = threadIdx.x;
    const int warp = tid >> 5, lane = tid & 31;
    const int wm = warp >> 2, wn = warp & 3;

    unsigned sbase = (unsigned)__cvta_generic_to_shared(dyn1);

    float acc[4][4][4];
#pragma unroll
    for (int i = 0; i < 4; i++)
#pragma unroll
        for (int j = 0; j < 4; j++)
#pragma unroll
            for (int r = 0; r < 4; r++) acc[i][j][r] = 0.f;

    const float* srcA = &x[(size_t)m0 * IN_];
    const float* srcB = &W[(size_t)n0 * IN_];

    float4 rA[4], rB[4];
    ldg_rm(srcA, IN_, tid, rA);
    ldg_rm(srcB, IN_, tid, rB);
    sts_rm(rA, dyn1 + 0 * RM_BUF_HALVES, dyn1 + 1 * RM_BUF_HALVES, tid);
    sts_rm(rB, dyn1 + 2 * RM_BUF_HALVES, dyn1 + 3 * RM_BUF_HALVES, tid);
    __syncthreads();

#define NK1 8
#pragma unroll
    for (int k = 0; k < NK1; k++) {
        const int st = k & 1;
        if (k + 1 < NK1) {
            ldg_rm(srcA + (k + 1) * 32, IN_, tid, rA);
            ldg_rm(srcB + (k + 1) * 32, IN_, tid, rB);
        }
        unsigned b0 = sbase + (unsigned)(st * 4) * RM_BUF_BYTES;
        mma_step_rm(b0, b0 + RM_BUF_BYTES, b0 + 2 * RM_BUF_BYTES,
                    b0 + 3 * RM_BUF_BYTES, wm, wn, lane, acc);
        if (k + 1 < NK1) {
            int st2 = (k + 1) & 1;
            sts_rm(rA, dyn1 + (st2 * 4 + 0) * RM_BUF_HALVES,
                   dyn1 + (st2 * 4 + 1) * RM_BUF_HALVES, tid);
            sts_rm(rB, dyn1 + (st2 * 4 + 2) * RM_BUF_HALVES,
                   dyn1 + (st2 * 4 + 3) * RM_BUF_HALVES, tid);
        }
        __syncthreads();
    }
    epilogue(&g_i[(size_t)m0 * H2_ + n0], H2_, 1.f, wm, wn, lane, acc);
}

// ---------------------------------------------------------------------------
// K2: key-side elementwise scan
// ---------------------------------------------------------------------------
__global__ __launch_bounds__(256) void k2_scan_key(float* __restrict__ out)
{
    const int b  = blockIdx.x / 3;
    const int h  = (blockIdx.x % 3) * 256 + threadIdx.x;

    const float* ik = &g_i[(b * T_) * H2_ + h];
    float* keyp  = &g_key[(b * T_) * H_ + h];
    float* ktrp  = &g_ktr[(b * T_) * H_ + h];
    float* keyso = &out[OUT_KEYS_ + (b * T_) * H_ + h];

    float kv = 0.f, ktr = 0.f;
#pragma unroll 4
    for (int t = 0; t < T_; t++) {
        kv = ALPHA_ * kv + OMA_ * ik[t * H2_];
        float key = tanh_fast(kv);
        ktr = DTR_ * ktr + OMD_ * key;
        keyp[t * H_]  = key;
        ktrp[t * H_]  = ktr;
        keyso[t * H_] = key;
    }
}

// ---------------------------------------------------------------------------
// K3: Apart[p][b][t][s] = sum_{k in chunk p} key[b,t,k]*ktr[b,s,k]
//     grid (6,32). M=N=128, K=128 (NK=4). Same pipeline as K1.
// ---------------------------------------------------------------------------
__global__ __launch_bounds__(256) void k3_gemm_A()
{
    extern __shared__ __nv_bfloat16 dyn3[];
    const int p = blockIdx.x;
    const int b = blockIdx.y;
    const int tid = threadIdx.x;
    const int warp = tid >> 5, lane = tid & 31;
    const int wm = warp >> 2, wn = warp & 3;

    unsigned sbase = (unsigned)__cvta_generic_to_shared(dyn3);

    const float* keyb = &g_key[(size_t)b * T_ * H_ + p * 128];
    const float* ktrb = &g_ktr[(size_t)b * T_ * H_ + p * 128];

    float acc[4][4][4];
#pragma unroll
    for (int i = 0; i < 4; i++)
#pragma unroll
        for (int j = 0; j < 4; j++)
#pragma unroll
            for (int r = 0; r < 4; r++) acc[i][j][r] = 0.f;

    float4 rA[4], rB[4];
    ldg_rm(keyb, H_, tid, rA);
    ldg_rm(ktrb, H_, tid, rB);
    sts_rm(rA, dyn3 + 0 * RM_BUF_HALVES, dyn3 + 1 * RM_BUF_HALVES, tid);
    sts_rm(rB, dyn3 + 2 * RM_BUF_HALVES, dyn3 + 3 * RM_BUF_HALVES, tid);
    __syncthreads();

#define NK3 4
#pragma unroll
    for (int k = 0; k < NK3; k++) {
        const int st = k & 1;
        if (k + 1 < NK3) {
            ldg_rm(keyb + (k + 1) * 32, H_, tid, rA);
            ldg_rm(ktrb + (k + 1) * 32, H_, tid, rB);
        }
        unsigned b0 = sbase + (unsigned)(st * 4) * RM_BUF_BYTES;
        mma_step_rm(b0, b0 + RM_BUF_BYTES, b0 + 2 * RM_BUF_BYTES,
                    b0 + 3 * RM_BUF_BYTES, wm, wn, lane, acc);
        if (k + 1 < NK3) {
            int st2 = (k + 1) & 1;
            sts_rm(rA, dyn3 + (st2 * 4 + 0) * RM_BUF_HALVES,
                   dyn3 + (st2 * 4 + 1) * RM_BUF_HALVES, tid);
            sts_rm(rB, dyn3 + (st2 * 4 + 2) * RM_BUF_HALVES,
                   dyn3 + (st2 * 4 + 3) * RM_BUF_HALVES, tid);
        }
        __syncthreads();
    }
    epilogue(&g_Apart[(size_t)(p * B_ + b) * (T_ * T_)], T_, 1.f, wm, wn, lane, acc);
}

// ---------------------------------------------------------------------------
// K4: value-side blocked sequential scan, s-SPLIT across thread pairs.
//     512 threads: tid&255 = h lane, tid>>8 = s-half. Cross-phase work for
//     each h is split between the pair; partials combined via smem. Intra
//     (serial) phase runs on the owner (half 0) only.
//     Dyn smem: A 64KB + vtr 128KB + partials 16KB = 208KB.
// ---------------------------------------------------------------------------
#define K4_BLK 16

__global__ __launch_bounds__(512) void k4_scan_val(float* __restrict__ out)
{
    extern __shared__ float sm4[];
    float* A_s   = sm4;                    // 16384
    float* vtr_s = sm4 + 16384;            // 128*256
    float* p_s   = sm4 + 16384 + 32768;    // 16*256

    const int b   = blockIdx.x / 3;
    const int hb  = blockIdx.x % 3;
    const int tid = threadIdx.x;
    const int lh  = tid & 255;
    const int half = tid >> 8;
    const int h   = hb * 256 + lh;

    // sum the 6 K-split partials of A into smem (512 threads)
    {
        const float* ap = &g_Apart[(size_t)b * (T_ * T_)];
        for (int e = tid * 4; e < T_ * T_; e += 512 * 4) {
            float4 s = *(const float4*)&ap[e];
#pragma unroll
            for (int p = 1; p < 6; p++) {
                float4 v = *(const float4*)&ap[(size_t)p * B_ * T_ * T_ + e];
                s.x += v.x; s.y += v.y; s.z += v.z; s.w += v.w;
            }
            *(float4*)&A_s[e] = s;
        }
    }
    __syncthreads();

    const float* ivp = &g_i[b * T_ * H2_ + H_ + h];
    float* valso = &out[OUT_VALS_ + (b * T_) * H_ + h];
    float* vtrg  = &g_vtr[(b * T_) * H_ + h];

    float vv = 0.f, vtr = 0.f;

    for (int t0 = 0; t0 < T_; t0 += K4_BLK) {
        const int mid  = t0 >> 1;               // multiple of 8
        const int sbeg = half ? mid : 0;
        const int send = half ? t0  : mid;

        float acc[K4_BLK];
#pragma unroll
        for (int j = 0; j < K4_BLK; j++) acc[j] = 0.f;

        for (int s4 = sbeg; s4 < send; s4 += 4) {
            float v0 = vtr_s[(s4 + 0) * 256 + lh];
            float v1 = vtr_s[(s4 + 1) * 256 + lh];
            float v2 = vtr_s[(s4 + 2) * 256 + lh];
            float v3 = vtr_s[(s4 + 3) * 256 + lh];
#pragma unroll
            for (int j = 0; j < K4_BLK; j++) {
                float4 a = *(const float4*)&A_s[(t0 + j) * T_ + s4];
                acc[j] = fmaf(a.x, v0, acc[j]);
                acc[j] = fmaf(a.y, v1, acc[j]);
                acc[j] = fmaf(a.z, v2, acc[j]);
                acc[j] = fmaf(a.w, v3, acc[j]);
            }
        }

        if (half) {
#pragma unroll
            for (int j = 0; j < K4_BLK; j++) p_s[j * 256 + lh] = acc[j];
        }
        __syncthreads();

        if (!half) {
#pragma unroll
            for (int j = 0; j < K4_BLK; j++) {
                const int t = t0 + j;
                float a = acc[j] + p_s[j * 256 + lh];
                const float* Arow = &A_s[t * T_];
                for (int s = t0; s < t; s++)
                    a = fmaf(Arow[s], vtr_s[s * 256 + lh], a);
                float ikv = CIKV_ * a;

                vv = ALPHA_ * vv + OMA_ * (ivp[t * H2_] + ikv);
                float val = tanh_fast(vv);
                valso[t * H_] = val;
                vtr = DTR_ * vtr + OMD_ * val;
                vtr_s[t * 256 + lh] = vtr;
                vtrg[t * H_] = vtr;
            }
        }
        __syncthreads();
    }
}

// ---------------------------------------------------------------------------
// K5: mem[b][i][j] = eta * sum_s vtr[b,s,i]*ktr[b,s,j]
//     k-major operands, trans-ldmatrix, 2-stage pipeline. grid (6,6,32), NK=4.
//     Dyn smem: 8 bufs x 8704B = 69.6KB.
// ---------------------------------------------------------------------------
__global__ __launch_bounds__(256) void k5_gemm_mem(float* __restrict__ out)
{
    extern __shared__ __nv_bfloat16 dyn5[];
    const int b  = blockIdx.z;
    const int i0 = blockIdx.y * 128;
    const int j0 = blockIdx.x * 128;
    const int tid = threadIdx.x;
    const int warp = tid >> 5, lane = tid & 31;
    const int wm = warp >> 2, wn = warp & 3;

    unsigned sbase = (unsigned)__cvta_generic_to_shared(dyn5);

    const float* srcA = &g_vtr[(size_t)b * T_ * H_ + i0];
    const float* srcB = &g_ktr[(size_t)b * T_ * H_ + j0];

    float acc[4][4][4];
#pragma unroll
    for (int i = 0; i < 4; i++)
#pragma unroll
        for (int j = 0; j < 4; j++)
#pragma unroll
            for (int r = 0; r < 4; r++) acc[i][j][r] = 0.f;

    float4 rA[4], rB[4];
    ldg_km(srcA, H_, tid, rA);
    ldg_km(srcB, H_, tid, rB);
    sts_km(rA, dyn5 + 0 * KM_BUF_HALVES, dyn5 + 1 * KM_BUF_HALVES, tid);
    sts_km(rB, dyn5 + 2 * KM_BUF_HALVES, dyn5 + 3 * KM_BUF_HALVES, tid);
    __syncthreads();

#define NK5 4
#pragma unroll
    for (int k = 0; k < NK5; k++) {
        const int st = k & 1;
        if (k + 1 < NK5) {
            ldg_km(srcA + (size_t)(k + 1) * 32 * H_, H_, tid, rA);
            ldg_km(srcB + (size_t)(k + 1) * 32 * H_, H_, tid, rB);
        }
        unsigned b0 = sbase + (unsigned)(st * 4) * KM_BUF_BYTES;
        mma_step_km(b0, b0 + KM_BUF_BYTES, b0 + 2 * KM_BUF_BYTES,
                    b0 + 3 * KM_BUF_BYTES, wm, wn, lane, acc);
        if (k + 1 < NK5) {
            int st2 = (k + 1) & 1;
            sts_km(rA, dyn5 + (st2 * 4 + 0) * KM_BUF_HALVES,
                   dyn5 + (st2 * 4 + 1) * KM_BUF_HALVES, tid);
            sts_km(rB, dyn5 + (st2 * 4 + 2) * KM_BUF_HALVES,
                   dyn5 + (st2 * 4 + 3) * KM_BUF_HALVES, tid);
        }
        __syncthreads();
    }
    epilogue(&out[(size_t)b * (H_ * H_) + (size_t)i0 * H_ + j0], H_, ETA_,
             wm, wn, lane, acc);
}

// ---------------------------------------------------------------------------
extern "C" void kernel_launch(void* const* d_in, const int* in_sizes, int n_in,
                              void* d_out, int out_size)
{
    const float* x = (const float*)d_in[0];   // (32,128,256)
    const float* W = (const float*)d_in[1];   // (1536,256)
    float* out = (float*)d_out;               // mem | keys | vals

    const int smem_rm = 8 * RM_BUF_BYTES;     // 81920
    const int smem_km = 8 * KM_BUF_BYTES;     // 69632
    const int smem_k4 = (16384 + 32768 + 4096) * 4;  // 212992

    (void)cudaFuncSetAttribute(k1_gemm_in,
        cudaFuncAttributeMaxDynamicSharedMemorySize, smem_rm);
    (void)cudaFuncSetAttribute(k3_gemm_A,
        cudaFuncAttributeMaxDynamicSharedMemorySize, smem_rm);
    (void)cudaFuncSetAttribute(k5_gemm_mem,
        cudaFuncAttributeMaxDynamicSharedMemorySize, smem_km);
    (void)cudaFuncSetAttribute(k4_scan_val,
        cudaFuncAttributeMaxDynamicSharedMemorySize, smem_k4);

    k1_gemm_in<<<dim3(12, 32), 256, smem_rm>>>(x, W);
    k2_scan_key<<<96, 256>>>(out);
    k3_gemm_A<<<dim3(6, 32), 256, smem_rm>>>();
    k4_scan_val<<<96, 512, smem_k4>>>(out);
    k5_gemm_mem<<<dim3(6, 6, 32), 256, smem_km>>>(out);
}

// round 6
// speedup vs baseline: 1.3011x; 1.3011x over previous
#include <cuda_runtime.h>
#include <cuda_bf16.h>
#include <math.h>

// Problem constants
#define B_   32
#define T_   128
#define H_   768
#define IN_  256
#define H2_  1536

// exp(-1/20)
#define ALPHA_   0.951229424500714f
#define OMA_     0.048770575499286f
#define DTR_     0.951229424500714f
#define OMD_     0.048770575499286f
#define ETA_     0.1f
#define CIKV_    0.02f

// Output offsets (floats): mem | keys | vals
#define OUT_MEM_   0
#define OUT_KEYS_  18874368
#define OUT_VALS_  22020096

// Scratch
__device__ float g_i[B_ * T_ * H2_];
__device__ float g_key[B_ * T_ * H_];
__device__ float g_ktr[B_ * T_ * H_];
__device__ float g_vtr[B_ * T_ * H_];
__device__ float g_Apart[6 * B_ * T_ * T_];

__device__ __forceinline__ float tanh_fast(float x) {
    float y;
    asm("tanh.approx.f32 %0, %1;" : "=f"(y) : "f"(x));
    return y;
}

// ---------------------------------------------------------------------------
// mma.sync helpers (bf16 hi/lo split GEMM)  — R3 proven versions
// ---------------------------------------------------------------------------
__device__ __forceinline__ void ldsm_x4(unsigned addr, unsigned& r0, unsigned& r1,
                                        unsigned& r2, unsigned& r3) {
    asm volatile("ldmatrix.sync.aligned.m8n8.x4.shared.b16 {%0,%1,%2,%3}, [%4];"
                 : "=r"(r0), "=r"(r1), "=r"(r2), "=r"(r3) : "r"(addr));
}
__device__ __forceinline__ void ldsm_x4t(unsigned addr, unsigned& r0, unsigned& r1,
                                         unsigned& r2, unsigned& r3) {
    asm volatile("ldmatrix.sync.aligned.m8n8.x4.trans.shared.b16 {%0,%1,%2,%3}, [%4];"
                 : "=r"(r0), "=r"(r1), "=r"(r2), "=r"(r3) : "r"(addr));
}
__device__ __forceinline__ void mma16816(float* c, unsigned a0, unsigned a1,
                                         unsigned a2, unsigned a3,
                                         unsigned b0, unsigned b1) {
    asm volatile(
        "mma.sync.aligned.m16n8k16.row.col.f32.bf16.bf16.f32 "
        "{%0,%1,%2,%3}, {%4,%5,%6,%7}, {%8,%9}, {%0,%1,%2,%3};"
        : "+f"(c[0]), "+f"(c[1]), "+f"(c[2]), "+f"(c[3])
        : "r"(a0), "r"(a1), "r"(a2), "r"(a3), "r"(b0), "r"(b1));
}
__device__ __forceinline__ void split_bf16(float v, __nv_bfloat16& hi, __nv_bfloat16& lo) {
    hi = __float2bfloat16(v);
    lo = __float2bfloat16(v - __bfloat162float(hi));
}

#define SRM 40    // smem stride (halves) for row-major [m][k] tiles (128x32)
#define SKM 136   // smem stride (halves) for k-major [k][m] tiles (32x128)

// One BK=32 compute step: row-major smem tiles [128][SRM], no-trans ldmatrix.
__device__ __forceinline__ void mma_step_rm(
    unsigned bAh, unsigned bAl, unsigned bBh, unsigned bBl,
    int wm, int wn, int lane, float acc[4][4][4])
{
    const int lr = lane & 15;
    const int kh = (lane >> 4) * 8;
#pragma unroll
    for (int ks = 0; ks < 32; ks += 16) {
        unsigned ah[4][4], al[4][4], bh[4][2], bl[4][2];
#pragma unroll
        for (int i = 0; i < 4; i++) {
            unsigned off = 2u * ((wm * 64 + i * 16 + lr) * SRM + ks + kh);
            ldsm_x4(bAh + off, ah[i][0], ah[i][1], ah[i][2], ah[i][3]);
            ldsm_x4(bAl + off, al[i][0], al[i][1], al[i][2], al[i][3]);
        }
#pragma unroll
        for (int p = 0; p < 2; p++) {
            unsigned off = 2u * ((wn * 32 + p * 16 + lr) * SRM + ks + kh);
            unsigned r0, r1, r2, r3;
            ldsm_x4(bBh + off, r0, r1, r2, r3);
            bh[p * 2 + 0][0] = r0; bh[p * 2 + 0][1] = r2;
            bh[p * 2 + 1][0] = r1; bh[p * 2 + 1][1] = r3;
            ldsm_x4(bBl + off, r0, r1, r2, r3);
            bl[p * 2 + 0][0] = r0; bl[p * 2 + 0][1] = r2;
            bl[p * 2 + 1][0] = r1; bl[p * 2 + 1][1] = r3;
        }
#pragma unroll
        for (int i = 0; i < 4; i++)
#pragma unroll
            for (int j = 0; j < 4; j++) {
                mma16816(acc[i][j], ah[i][0], ah[i][1], ah[i][2], ah[i][3],
                         bh[j][0], bh[j][1]);
                mma16816(acc[i][j], ah[i][0], ah[i][1], ah[i][2], ah[i][3],
                         bl[j][0], bl[j][1]);
                mma16816(acc[i][j], al[i][0], al[i][1], al[i][2], al[i][3],
                         bh[j][0], bh[j][1]);
            }
    }
}

// One BK=32 compute step: k-major smem tiles [32][SKM], trans ldmatrix.
__device__ __forceinline__ void mma_step_km(
    unsigned bAh, unsigned bAl, unsigned bBh, unsigned bBl,
    int wm, int wn, int lane, float acc[4][4][4])
{
    const int krow = (lane & 7) + ((lane >> 4) << 3);
    const int mcol = ((lane >> 3) & 1) * 8;
#pragma unroll
    for (int ks = 0; ks < 32; ks += 16) {
        unsigned ah[4][4], al[4][4], bh[4][2], bl[4][2];
#pragma unroll
        for (int i = 0; i < 4; i++) {
            unsigned off = 2u * ((ks + krow) * SKM + wm * 64 + i * 16 + mcol);
            ldsm_x4t(bAh + off, ah[i][0], ah[i][1], ah[i][2], ah[i][3]);
            ldsm_x4t(bAl + off, al[i][0], al[i][1], al[i][2], al[i][3]);
        }
#pragma unroll
        for (int p = 0; p < 2; p++) {
            unsigned off = 2u * ((ks + krow) * SKM + wn * 32 + p * 16 + mcol);
            unsigned r0, r1, r2, r3;
            ldsm_x4t(bBh + off, r0, r1, r2, r3);
            bh[p * 2 + 0][0] = r0; bh[p * 2 + 0][1] = r2;
            bh[p * 2 + 1][0] = r1; bh[p * 2 + 1][1] = r3;
            ldsm_x4t(bBl + off, r0, r1, r2, r3);
            bl[p * 2 + 0][0] = r0; bl[p * 2 + 0][1] = r2;
            bl[p * 2 + 1][0] = r1; bl[p * 2 + 1][1] = r3;
        }
#pragma unroll
        for (int i = 0; i < 4; i++)
#pragma unroll
            for (int j = 0; j < 4; j++) {
                mma16816(acc[i][j], ah[i][0], ah[i][1], ah[i][2], ah[i][3],
                         bh[j][0], bh[j][1]);
                mma16816(acc[i][j], ah[i][0], ah[i][1], ah[i][2], ah[i][3],
                         bl[j][0], bl[j][1]);
                mma16816(acc[i][j], al[i][0], al[i][1], al[i][2], al[i][3],
                         bh[j][0], bh[j][1]);
            }
    }
}

// Row-major loader: 128 rows x 32 k from gmem (ld = row stride in f32).
__device__ __forceinline__ void load_rm(const float* __restrict__ src, int ld,
                                        __nv_bfloat16* sh, __nv_bfloat16* sl,
                                        int tid)
{
#pragma unroll
    for (int l = 0; l < 4; l++) {
        int idx = tid + l * 256;
        int row = idx >> 3;
        int c4  = idx & 7;
        float4 v = *(const float4*)&src[row * ld + c4 * 4];
        __nv_bfloat16 h0, l0, h1, l1, h2, l2, h3, l3;
        split_bf16(v.x, h0, l0); split_bf16(v.y, h1, l1);
        split_bf16(v.z, h2, l2); split_bf16(v.w, h3, l3);
        int o = row * SRM + c4 * 4;
        sh[o + 0] = h0; sh[o + 1] = h1; sh[o + 2] = h2; sh[o + 3] = h3;
        sl[o + 0] = l0; sl[o + 1] = l1; sl[o + 2] = l2; sl[o + 3] = l3;
    }
}

// K-major loader: 32 k-rows x 128 m from gmem [k][m].
__device__ __forceinline__ void load_km(const float* __restrict__ src, int ld,
                                        __nv_bfloat16* sh, __nv_bfloat16* sl,
                                        int tid)
{
#pragma unroll
    for (int l = 0; l < 4; l++) {
        int idx = tid + l * 256;
        int s = idx >> 5;
        int q = idx & 31;
        float4 v = *(const float4*)&src[s * ld + q * 4];
        __nv_bfloat16 h0, l0, h1, l1, h2, l2, h3, l3;
        split_bf16(v.x, h0, l0); split_bf16(v.y, h1, l1);
        split_bf16(v.z, h2, l2); split_bf16(v.w, h3, l3);
        int o = s * SKM + q * 4;
        sh[o + 0] = h0; sh[o + 1] = h1; sh[o + 2] = h2; sh[o + 3] = h3;
        sl[o + 0] = l0; sl[o + 1] = l1; sl[o + 2] = l2; sl[o + 3] = l3;
    }
}

// Epilogue: write 4x4 m16n8 tiles to gmem, scaled.
__device__ __forceinline__ void epilogue(float* dst, int ldc, float scale,
                                         int wm, int wn, int lane,
                                         float acc[4][4][4])
{
    const int r0 = lane >> 2;
    const int c0 = (lane & 3) * 2;
#pragma unroll
    for (int i = 0; i < 4; i++)
#pragma unroll
        for (int j = 0; j < 4; j++) {
            int row = wm * 64 + i * 16 + r0;
            int col = wn * 32 + j * 8 + c0;
            float2 v0 = make_float2(scale * acc[i][j][0], scale * acc[i][j][1]);
            float2 v1 = make_float2(scale * acc[i][j][2], scale * acc[i][j][3]);
            *(float2*)&dst[row * ldc + col] = v0;
            *(float2*)&dst[(row + 8) * ldc + col] = v1;
        }
}

// ---------------------------------------------------------------------------
// K1: g_i[m][n] = sum_k x[m][k] * W[n][k]   M=4096 N=1536 K=256
// ---------------------------------------------------------------------------
__global__ __launch_bounds__(256) void k1_gemm_in(
    const float* __restrict__ x, const float* __restrict__ W)
{
    __shared__ __nv_bfloat16 sAh[128 * SRM], sAl[128 * SRM];
    __shared__ __nv_bfloat16 sBh[128 * SRM], sBl[128 * SRM];

    const int m0 = blockIdx.y * 128;
    const int n0 = blockIdx.x * 128;
    const int tid = threadIdx.x;
    const int warp = tid >> 5, lane = tid & 31;
    const int wm = warp >> 2, wn = warp & 3;

    unsigned bAh = (unsigned)__cvta_generic_to_shared(sAh);
    unsigned bAl = (unsigned)__cvta_generic_to_shared(sAl);
    unsigned bBh = (unsigned)__cvta_generic_to_shared(sBh);
    unsigned bBl = (unsigned)__cvta_generic_to_shared(sBl);

    float acc[4][4][4];
#pragma unroll
    for (int i = 0; i < 4; i++)
#pragma unroll
        for (int j = 0; j < 4; j++)
#pragma unroll
            for (int r = 0; r < 4; r++) acc[i][j][r] = 0.f;

    for (int k0 = 0; k0 < IN_; k0 += 32) {
        load_rm(&x[(size_t)m0 * IN_ + k0], IN_, sAh, sAl, tid);
        load_rm(&W[(size_t)n0 * IN_ + k0], IN_, sBh, sBl, tid);
        __syncthreads();
        mma_step_rm(bAh, bAl, bBh, bBl, wm, wn, lane, acc);
        __syncthreads();
    }
    epilogue(&g_i[(size_t)m0 * H2_ + n0], H2_, 1.f, wm, wn, lane, acc);
}

// ---------------------------------------------------------------------------
// K2: key-side elementwise scan
// ---------------------------------------------------------------------------
__global__ __launch_bounds__(256) void k2_scan_key(float* __restrict__ out)
{
    const int b  = blockIdx.x / 3;
    const int h  = (blockIdx.x % 3) * 256 + threadIdx.x;

    const float* ik = &g_i[(b * T_) * H2_ + h];
    float* keyp  = &g_key[(b * T_) * H_ + h];
    float* ktrp  = &g_ktr[(b * T_) * H_ + h];
    float* keyso = &out[OUT_KEYS_ + (b * T_) * H_ + h];

    float kv = 0.f, ktr = 0.f;
#pragma unroll 4
    for (int t = 0; t < T_; t++) {
        kv = ALPHA_ * kv + OMA_ * ik[t * H2_];
        float key = tanh_fast(kv);
        ktr = DTR_ * ktr + OMD_ * key;
        keyp[t * H_]  = key;
        ktrp[t * H_]  = ktr;
        keyso[t * H_] = key;
    }
}

// ---------------------------------------------------------------------------
// K3: Apart[p][b][t][s] = sum_{k in chunk p} key[b,t,k]*ktr[b,s,k]
// ---------------------------------------------------------------------------
__global__ __launch_bounds__(256) void k3_gemm_A()
{
    __shared__ __nv_bfloat16 sAh[128 * SRM], sAl[128 * SRM];
    __shared__ __nv_bfloat16 sBh[128 * SRM], sBl[128 * SRM];

    const int p = blockIdx.x;
    const int b = blockIdx.y;
    const int tid = threadIdx.x;
    const int warp = tid >> 5, lane = tid & 31;
    const int wm = warp >> 2, wn = warp & 3;

    unsigned bAh = (unsigned)__cvta_generic_to_shared(sAh);
    unsigned bAl = (unsigned)__cvta_generic_to_shared(sAl);
    unsigned bBh = (unsigned)__cvta_generic_to_shared(sBh);
    unsigned bBl = (unsigned)__cvta_generic_to_shared(sBl);

    const float* keyb = &g_key[(size_t)b * T_ * H_ + p * 128];
    const float* ktrb = &g_ktr[(size_t)b * T_ * H_ + p * 128];

    float acc[4][4][4];
#pragma unroll
    for (int i = 0; i < 4; i++)
#pragma unroll
        for (int j = 0; j < 4; j++)
#pragma unroll
            for (int r = 0; r < 4; r++) acc[i][j][r] = 0.f;

    for (int k0 = 0; k0 < 128; k0 += 32) {
        load_rm(&keyb[k0], H_, sAh, sAl, tid);
        load_rm(&ktrb[k0], H_, sBh, sBl, tid);
        __syncthreads();
        mma_step_rm(bAh, bAl, bBh, bBl, wm, wn, lane, acc);
        __syncthreads();
    }
    epilogue(&g_Apart[(size_t)(p * B_ + b) * (T_ * T_)], T_, 1.f, wm, wn, lane, acc);
}

// ---------------------------------------------------------------------------
// K4: value-side scan, warp-autonomous.
//     512 threads = 16 warps. Warp w owns 16 h-channels: lh = w*16 + (lane&15),
//     half = lane>>4 splits the cross-phase s-range. Partials combined via
//     shfl_xor(16); intra-block triangle computed redundantly by both halves
//     entirely in registers (vtr_blk). NO __syncthreads in the main loop —
//     only __syncwarp per t-block for vtr_s visibility.
//     Dyn smem: A 64KB + vtr[128][256] 128KB = 192KB.
// ---------------------------------------------------------------------------
#define K4_BLK 16

__global__ __launch_bounds__(512) void k4_scan_val(float* __restrict__ out)
{
    extern __shared__ float sm4[];
    float* A_s   = sm4;            // [t][s] 128*128
    float* vtr_s = sm4 + 16384;    // [s][lh] 128*256

    const int b    = blockIdx.x / 3;
    const int hb   = blockIdx.x % 3;
    const int tid  = threadIdx.x;
    const int warp = tid >> 5;
    const int lane = tid & 31;
    const int lr   = lane & 15;
    const int half = lane >> 4;
    const int lh   = warp * 16 + lr;      // 0..255
    const int h    = hb * 256 + lh;

    // sum the 6 K-split partials of A into smem (512 threads), then one sync
    {
        const float* ap = &g_Apart[(size_t)b * (T_ * T_)];
        for (int e = tid * 4; e < T_ * T_; e += 512 * 4) {
            float4 s = *(const float4*)&ap[e];
#pragma unroll
            for (int p = 1; p < 6; p++) {
                float4 v = *(const float4*)&ap[(size_t)p * B_ * T_ * T_ + e];
                s.x += v.x; s.y += v.y; s.z += v.z; s.w += v.w;
            }
            *(float4*)&A_s[e] = s;
        }
    }
    __syncthreads();

    const float* ivp = &g_i[b * T_ * H2_ + H_ + h];
    float* valso = &out[OUT_VALS_ + (b * T_) * H_ + h];
    float* vtrg  = &g_vtr[(b * T_) * H_ + h];

    float vv = 0.f, vtr = 0.f;

    for (int t0 = 0; t0 < T_; t0 += K4_BLK) {
        // preload this block's iv inputs (independent gmem loads)
        float iv_blk[K4_BLK];
#pragma unroll
        for (int j = 0; j < K4_BLK; j++) iv_blk[j] = ivp[(t0 + j) * H2_];

        // ---- cross phase: halves split s in [0,t0) ----
        const int mid  = t0 >> 1;            // multiple of 8
        const int sbeg = half ? mid : 0;
        const int send = half ? t0  : mid;

        float acc[K4_BLK];
#pragma unroll
        for (int j = 0; j < K4_BLK; j++) acc[j] = 0.f;

        for (int s4 = sbeg; s4 < send; s4 += 4) {
            float v0 = vtr_s[(s4 + 0) * 256 + lh];
            float v1 = vtr_s[(s4 + 1) * 256 + lh];
            float v2 = vtr_s[(s4 + 2) * 256 + lh];
            float v3 = vtr_s[(s4 + 3) * 256 + lh];
#pragma unroll
            for (int j = 0; j < K4_BLK; j++) {
                float4 a = *(const float4*)&A_s[(t0 + j) * T_ + s4];
                acc[j] = fmaf(a.x, v0, acc[j]);
                acc[j] = fmaf(a.y, v1, acc[j]);
                acc[j] = fmaf(a.z, v2, acc[j]);
                acc[j] = fmaf(a.w, v3, acc[j]);
            }
        }
        // combine halves within the warp
#pragma unroll
        for (int j = 0; j < K4_BLK; j++)
            acc[j] += __shfl_xor_sync(0xFFFFFFFFu, acc[j], 16);

        // ---- intra phase: fully register-resident, run by BOTH halves ----
        float vtr_blk[K4_BLK];
#pragma unroll
        for (int j = 0; j < K4_BLK; j++) {
            const int t = t0 + j;
            float a = acc[j];
            const float* Arow = &A_s[t * T_ + t0];
#pragma unroll
            for (int sj = 0; sj < j; sj++)
                a = fmaf(Arow[sj], vtr_blk[sj], a);
            float ikv = CIKV_ * a;

            vv = ALPHA_ * vv + OMA_ * (iv_blk[j] + ikv);
            float val = tanh_fast(vv);
            vtr = DTR_ * vtr + OMD_ * val;
            vtr_blk[j] = vtr;
            if (!half) {
                valso[t * H_] = val;
                vtr_s[t * 256 + lh] = vtr;
                vtrg[t * H_] = vtr;
            }
        }
        __syncwarp();   // vtr_s writes visible to half 1 before next cross phase
    }
}

// ---------------------------------------------------------------------------
// K5: mem[b][i][j] = eta * sum_s vtr[b,s,i]*ktr[b,s,j]
//     k-major operands -> trans-ldmatrix path. grid (6,6,32).
// ---------------------------------------------------------------------------
__global__ __launch_bounds__(256) void k5_gemm_mem(float* __restrict__ out)
{
    __shared__ __nv_bfloat16 sAh[32 * SKM], sAl[32 * SKM];
    __shared__ __nv_bfloat16 sBh[32 * SKM], sBl[32 * SKM];

    const int b  = blockIdx.z;
    const int i0 = blockIdx.y * 128;
    const int j0 = blockIdx.x * 128;
    const int tid = threadIdx.x;
    const int warp = tid >> 5, lane = tid & 31;
    const int wm = warp >> 2, wn = warp & 3;

    unsigned bAh = (unsigned)__cvta_generic_to_shared(sAh);
    unsigned bAl = (unsigned)__cvta_generic_to_shared(sAl);
    unsigned bBh = (unsigned)__cvta_generic_to_shared(sBh);
    unsigned bBl = (unsigned)__cvta_generic_to_shared(sBl);

    const float* vtrb = &g_vtr[(size_t)b * T_ * H_];
    const float* ktrb = &g_ktr[(size_t)b * T_ * H_];

    float acc[4][4][4];
#pragma unroll
    for (int i = 0; i < 4; i++)
#pragma unroll
        for (int j = 0; j < 4; j++)
#pragma unroll
            for (int r = 0; r < 4; r++) acc[i][j][r] = 0.f;

    for (int s0 = 0; s0 < T_; s0 += 32) {
        load_km(&vtrb[(size_t)s0 * H_ + i0], H_, sAh, sAl, tid);
        load_km(&ktrb[(size_t)s0 * H_ + j0], H_, sBh, sBl, tid);
        __syncthreads();
        mma_step_km(bAh, bAl, bBh, bBl, wm, wn, lane, acc);
        __syncthreads();
    }
    epilogue(&out[(size_t)b * (H_ * H_) + (size_t)i0 * H_ + j0], H_, ETA_,
             wm, wn, lane, acc);
}

// ---------------------------------------------------------------------------
extern "C" void kernel_launch(void* const* d_in, const int* in_sizes, int n_in,
                              void* d_out, int out_size)
{
    const float* x = (const float*)d_in[0];   // (32,128,256)
    const float* W = (const float*)d_in[1];   // (1536,256)
    float* out = (float*)d_out;               // mem | keys | vals

    const int smem_k4 = (16384 + 32768) * 4;  // 196608

    (void)cudaFuncSetAttribute(k4_scan_val,
        cudaFuncAttributeMaxDynamicSharedMemorySize, smem_k4);

    k1_gemm_in<<<dim3(12, 32), 256>>>(x, W);
    k2_scan_key<<<96, 256>>>(out);
    k3_gemm_A<<<dim3(6, 32), 256>>>();
    k4_scan_val<<<96, 512, smem_k4>>>(out);
    k5_gemm_mem<<<dim3(6, 6, 32), 256>>>(out);
}

// round 7
// speedup vs baseline: 1.3170x; 1.0122x over previous
#include <cuda_runtime.h>
#include <cuda_bf16.h>
#include <math.h>

// Problem constants
#define B_   32
#define T_   128
#define H_   768
#define IN_  256
#define H2_  1536

// exp(-1/20)
#define ALPHA_   0.951229424500714f
#define OMA_     0.048770575499286f
#define DTR_     0.951229424500714f
#define OMD_     0.048770575499286f
#define ETA_     0.1f
#define CIKV_    0.02f

// Output offsets (floats): mem | keys | vals
#define OUT_MEM_   0
#define OUT_KEYS_  18874368
#define OUT_VALS_  22020096

// Scratch (f32)
__device__ float g_i[B_ * T_ * H2_];
__device__ float g_Apart[6 * B_ * T_ * T_];

// Pre-split bf16 hi/lo operand arrays
__device__ __nv_bfloat16 g_xh[B_ * T_ * IN_],  g_xl[B_ * T_ * IN_];
__device__ __nv_bfloat16 g_Wh[H2_ * IN_],      g_Wl[H2_ * IN_];
__device__ __nv_bfloat16 g_keyh[B_ * T_ * H_], g_keyl[B_ * T_ * H_];
__device__ __nv_bfloat16 g_ktrh[B_ * T_ * H_], g_ktrl[B_ * T_ * H_];
__device__ __nv_bfloat16 g_vtrh[B_ * T_ * H_], g_vtrl[B_ * T_ * H_];

__device__ __forceinline__ float tanh_fast(float x) {
    float y;
    asm("tanh.approx.f32 %0, %1;" : "=f"(y) : "f"(x));
    return y;
}
__device__ __forceinline__ void split_bf16(float v, __nv_bfloat16& hi, __nv_bfloat16& lo) {
    hi = __float2bfloat16(v);
    lo = __float2bfloat16(v - __bfloat162float(hi));
}

// ---------------------------------------------------------------------------
// mma.sync helpers
// ---------------------------------------------------------------------------
__device__ __forceinline__ void ldsm_x4(unsigned addr, unsigned& r0, unsigned& r1,
                                        unsigned& r2, unsigned& r3) {
    asm volatile("ldmatrix.sync.aligned.m8n8.x4.shared.b16 {%0,%1,%2,%3}, [%4];"
                 : "=r"(r0), "=r"(r1), "=r"(r2), "=r"(r3) : "r"(addr));
}
__device__ __forceinline__ void ldsm_x4t(unsigned addr, unsigned& r0, unsigned& r1,
                                         unsigned& r2, unsigned& r3) {
    asm volatile("ldmatrix.sync.aligned.m8n8.x4.trans.shared.b16 {%0,%1,%2,%3}, [%4];"
                 : "=r"(r0), "=r"(r1), "=r"(r2), "=r"(r3) : "r"(addr));
}
__device__ __forceinline__ void mma16816(float* c, unsigned a0, unsigned a1,
                                         unsigned a2, unsigned a3,
                                         unsigned b0, unsigned b1) {
    asm volatile(
        "mma.sync.aligned.m16n8k16.row.col.f32.bf16.bf16.f32 "
        "{%0,%1,%2,%3}, {%4,%5,%6,%7}, {%8,%9}, {%0,%1,%2,%3};"
        : "+f"(c[0]), "+f"(c[1]), "+f"(c[2]), "+f"(c[3])
        : "r"(a0), "r"(a1), "r"(a2), "r"(a3), "r"(b0), "r"(b1));
}

// cp.async helpers
__device__ __forceinline__ void cp16(unsigned dst, const void* src) {
    asm volatile("cp.async.cg.shared.global [%0], [%1], 16;" :: "r"(dst), "l"(src));
}
#define CP_COMMIT() asm volatile("cp.async.commit_group;")
#define CP_WAIT0()  asm volatile("cp.async.wait_group 0;" ::: "memory")

#define SRM 40    // smem stride (halves) row-major tiles (128 rows x 32 k)
#define SKM 136   // smem stride (halves) k-major tiles (32 k x 128 m)
#define RM_BUF_HALVES (128 * SRM)           // 5120
#define RM_STAGE_HALVES (4 * RM_BUF_HALVES) // Ah,Al,Bh,Bl
#define KM_BUF_HALVES (32 * SKM)            // 4352
#define KM_STAGE_HALVES (4 * KM_BUF_HALVES)

// Copy one row-major 128x32 bf16 tile pair (hi,lo) into smem via cp.async.
// src rows stride ld (halves). 512 16B-chunks per buf -> 2 per thread per buf.
__device__ __forceinline__ void cpa_rm(unsigned dsth, const __nv_bfloat16* srch,
                                       unsigned dstl, const __nv_bfloat16* srcl,
                                       int ld, int tid)
{
#pragma unroll
    for (int l = 0; l < 2; l++) {
        int c = tid + l * 256;
        int row = c >> 2;
        int q   = c & 3;
        unsigned doff = (unsigned)(row * SRM * 2 + q * 16);
        const char* so = (const char*)srch + (size_t)row * ld * 2 + q * 16;
        cp16(dsth + doff, so);
        const char* so2 = (const char*)srcl + (size_t)row * ld * 2 + q * 16;
        cp16(dstl + doff, so2);
    }
}
// Copy one k-major 32x128 bf16 tile pair into smem. rows stride ld (halves).
__device__ __forceinline__ void cpa_km(unsigned dsth, const __nv_bfloat16* srch,
                                       unsigned dstl, const __nv_bfloat16* srcl,
                                       int ld, int tid)
{
#pragma unroll
    for (int l = 0; l < 2; l++) {
        int c = tid + l * 256;
        int row = c >> 4;
        int q   = c & 15;
        unsigned doff = (unsigned)(row * SKM * 2 + q * 16);
        const char* so = (const char*)srch + (size_t)row * ld * 2 + q * 16;
        cp16(dsth + doff, so);
        const char* so2 = (const char*)srcl + (size_t)row * ld * 2 + q * 16;
        cp16(dstl + doff, so2);
    }
}

// One BK=32 compute step: row-major smem tiles [128][SRM], no-trans ldmatrix.
__device__ __forceinline__ void mma_step_rm(
    unsigned bAh, unsigned bAl, unsigned bBh, unsigned bBl,
    int wm, int wn, int lane, float acc[4][4][4])
{
    const int lr = lane & 15;
    const int kh = (lane >> 4) * 8;
#pragma unroll
    for (int ks = 0; ks < 32; ks += 16) {
        unsigned ah[4][4], al[4][4], bh[4][2], bl[4][2];
#pragma unroll
        for (int i = 0; i < 4; i++) {
            unsigned off = 2u * ((wm * 64 + i * 16 + lr) * SRM + ks + kh);
            ldsm_x4(bAh + off, ah[i][0], ah[i][1], ah[i][2], ah[i][3]);
            ldsm_x4(bAl + off, al[i][0], al[i][1], al[i][2], al[i][3]);
        }
#pragma unroll
        for (int p = 0; p < 2; p++) {
            unsigned off = 2u * ((wn * 32 + p * 16 + lr) * SRM + ks + kh);
            unsigned r0, r1, r2, r3;
            ldsm_x4(bBh + off, r0, r1, r2, r3);
            bh[p * 2 + 0][0] = r0; bh[p * 2 + 0][1] = r2;
            bh[p * 2 + 1][0] = r1; bh[p * 2 + 1][1] = r3;
            ldsm_x4(bBl + off, r0, r1, r2, r3);
            bl[p * 2 + 0][0] = r0; bl[p * 2 + 0][1] = r2;
            bl[p * 2 + 1][0] = r1; bl[p * 2 + 1][1] = r3;
        }
#pragma unroll
        for (int i = 0; i < 4; i++)
#pragma unroll
            for (int j = 0; j < 4; j++) {
                mma16816(acc[i][j], ah[i][0], ah[i][1], ah[i][2], ah[i][3],
                         bh[j][0], bh[j][1]);
                mma16816(acc[i][j], ah[i][0], ah[i][1], ah[i][2], ah[i][3],
                         bl[j][0], bl[j][1]);
                mma16816(acc[i][j], al[i][0], al[i][1], al[i][2], al[i][3],
                         bh[j][0], bh[j][1]);
            }
    }
}

// One BK=32 compute step: k-major smem tiles [32][SKM], trans ldmatrix.
__device__ __forceinline__ void mma_step_km(
    unsigned bAh, unsigned bAl, unsigned bBh, unsigned bBl,
    int wm, int wn, int lane, float acc[4][4][4])
{
    const int krow = (lane & 7) + ((lane >> 4) << 3);
    const int mcol = ((lane >> 3) & 1) * 8;
#pragma unroll
    for (int ks = 0; ks < 32; ks += 16) {
        unsigned ah[4][4], al[4][4], bh[4][2], bl[4][2];
#pragma unroll
        for (int i = 0; i < 4; i++) {
            unsigned off = 2u * ((ks + krow) * SKM + wm * 64 + i * 16 + mcol);
            ldsm_x4t(bAh + off, ah[i][0], ah[i][1], ah[i][2], ah[i][3]);
            ldsm_x4t(bAl + off, al[i][0], al[i][1], al[i][2], al[i][3]);
        }
#pragma unroll
        for (int p = 0; p < 2; p++) {
            unsigned off = 2u * ((ks + krow) * SKM + wn * 32 + p * 16 + mcol);
            unsigned r0, r1, r2, r3;
            ldsm_x4t(bBh + off, r0, r1, r2, r3);
            bh[p * 2 + 0][0] = r0; bh[p * 2 + 0][1] = r2;
            bh[p * 2 + 1][0] = r1; bh[p * 2 + 1][1] = r3;
            ldsm_x4t(bBl + off, r0, r1, r2, r3);
            bl[p * 2 + 0][0] = r0; bl[p * 2 + 0][1] = r2;
            bl[p * 2 + 1][0] = r1; bl[p * 2 + 1][1] = r3;
        }
#pragma unroll
        for (int i = 0; i < 4; i++)
#pragma unroll
            for (int j = 0; j < 4; j++) {
                mma16816(acc[i][j], ah[i][0], ah[i][1], ah[i][2], ah[i][3],
                         bh[j][0], bh[j][1]);
                mma16816(acc[i][j], ah[i][0], ah[i][1], ah[i][2], ah[i][3],
                         bl[j][0], bl[j][1]);
                mma16816(acc[i][j], al[i][0], al[i][1], al[i][2], al[i][3],
                         bh[j][0], bh[j][1]);
            }
    }
}

// Epilogue: write 4x4 m16n8 tiles to gmem, scaled.
__device__ __forceinline__ void epilogue(float* dst, int ldc, float scale,
                                         int wm, int wn, int lane,
                                         float acc[4][4][4])
{
    const int r0 = lane >> 2;
    const int c0 = (lane & 3) * 2;
#pragma unroll
    for (int i = 0; i < 4; i++)
#pragma unroll
        for (int j = 0; j < 4; j++) {
            int row = wm * 64 + i * 16 + r0;
            int col = wn * 32 + j * 8 + c0;
            float2 v0 = make_float2(scale * acc[i][j][0], scale * acc[i][j][1]);
            float2 v1 = make_float2(scale * acc[i][j][2], scale * acc[i][j][3]);
            *(float2*)&dst[row * ldc + col] = v0;
            *(float2*)&dst[(row + 8) * ldc + col] = v1;
        }
}

// ---------------------------------------------------------------------------
// K0: pre-split x and W into hi/lo bf16
// ---------------------------------------------------------------------------
#define XN_ (B_ * T_ * IN_)   // 1048576
#define WN_ (H2_ * IN_)       // 393216

__global__ __launch_bounds__(256) void k0_convert(
    const float* __restrict__ x, const float* __restrict__ W)
{
    int i4 = (blockIdx.x * 256 + threadIdx.x) * 4;
    const float* src;
    __nv_bfloat16 *dh, *dl;
    int off;
    if (i4 < XN_) {
        src = x; dh = g_xh; dl = g_xl; off = i4;
    } else if (i4 < XN_ + WN_) {
        src = W; dh = g_Wh; dl = g_Wl; off = i4 - XN_;
    } else return;
    float4 v = *(const float4*)&src[off];
    __nv_bfloat16 h0, l0, h1, l1, h2, l2, h3, l3;
    split_bf16(v.x, h0, l0); split_bf16(v.y, h1, l1);
    split_bf16(v.z, h2, l2); split_bf16(v.w, h3, l3);
    dh[off + 0] = h0; dh[off + 1] = h1; dh[off + 2] = h2; dh[off + 3] = h3;
    dl[off + 0] = l0; dl[off + 1] = l1; dl[off + 2] = l2; dl[off + 3] = l3;
}

// ---------------------------------------------------------------------------
// K1: g_i[m][n] = sum_k x[m][k]*W[n][k]   M=4096 N=1536 K=256 (NK=8)
//     cp.async double-buffered, 1 sync/iter. Dyn smem 2*40KB = 80KB.
// ---------------------------------------------------------------------------
__global__ __launch_bounds__(256, 2) void k1_gemm_in()
{
    extern __shared__ __nv_bfloat16 dyn[];
    const int m0 = blockIdx.y * 128;
    const int n0 = blockIdx.x * 128;
    const int tid = threadIdx.x;
    const int warp = tid >> 5, lane = tid & 31;
    const int wm = warp >> 2, wn = warp & 3;

    unsigned sb = (unsigned)__cvta_generic_to_shared(dyn);

    float acc[4][4][4];
#pragma unroll
    for (int i = 0; i < 4; i++)
#pragma unroll
        for (int j = 0; j < 4; j++)
#pragma unroll
            for (int r = 0; r < 4; r++) acc[i][j][r] = 0.f;

    const __nv_bfloat16* Ah = &g_xh[(size_t)m0 * IN_];
    const __nv_bfloat16* Al = &g_xl[(size_t)m0 * IN_];
    const __nv_bfloat16* Bh = &g_Wh[(size_t)n0 * IN_];
    const __nv_bfloat16* Bl = &g_Wl[(size_t)n0 * IN_];

#define NK1 8
    // prologue: stage 0
    {
        unsigned s0 = sb;
        cpa_rm(s0, Ah, s0 + RM_BUF_HALVES * 2u, Al, IN_, tid);
        cpa_rm(s0 + RM_BUF_HALVES * 4u, Bh, s0 + RM_BUF_HALVES * 6u, Bl, IN_, tid);
        CP_COMMIT();
    }
    for (int k = 0; k < NK1; k++) {
        CP_WAIT0();
        __syncthreads();
        if (k + 1 < NK1) {
            unsigned s1 = sb + (unsigned)(((k + 1) & 1) * RM_STAGE_HALVES) * 2u;
            cpa_rm(s1, Ah + (k + 1) * 32, s1 + RM_BUF_HALVES * 2u, Al + (k + 1) * 32, IN_, tid);
            cpa_rm(s1 + RM_BUF_HALVES * 4u, Bh + (k + 1) * 32,
                   s1 + RM_BUF_HALVES * 6u, Bl + (k + 1) * 32, IN_, tid);
            CP_COMMIT();
        }
        unsigned s = sb + (unsigned)((k & 1) * RM_STAGE_HALVES) * 2u;
        mma_step_rm(s, s + RM_BUF_HALVES * 2u, s + RM_BUF_HALVES * 4u,
                    s + RM_BUF_HALVES * 6u, wm, wn, lane, acc);
    }
    epilogue(&g_i[(size_t)m0 * H2_ + n0], H2_, 1.f, wm, wn, lane, acc);
}

// ---------------------------------------------------------------------------
// K2: key-side elementwise scan; writes keys (f32 out) + hi/lo bf16 key/ktr
// ---------------------------------------------------------------------------
__global__ __launch_bounds__(256) void k2_scan_key(float* __restrict__ out)
{
    const int b  = blockIdx.x / 3;
    const int h  = (blockIdx.x % 3) * 256 + threadIdx.x;

    const float* ik = &g_i[(b * T_) * H2_ + h];
    const int base = (b * T_) * H_ + h;
    float* keyso = &out[OUT_KEYS_ + base];

    float kv = 0.f, ktr = 0.f;
#pragma unroll 4
    for (int t = 0; t < T_; t++) {
        kv = ALPHA_ * kv + OMA_ * ik[t * H2_];
        float key = tanh_fast(kv);
        ktr = DTR_ * ktr + OMD_ * key;
        keyso[t * H_] = key;
        __nv_bfloat16 hh, ll;
        split_bf16(key, hh, ll);
        g_keyh[base + t * H_] = hh; g_keyl[base + t * H_] = ll;
        split_bf16(ktr, hh, ll);
        g_ktrh[base + t * H_] = hh; g_ktrl[base + t * H_] = ll;
    }
}

// ---------------------------------------------------------------------------
// K3: Apart[p][b][t][s] = sum_{k in chunk p} key[b,t,k]*ktr[b,s,k]
//     grid (6,32). NK=4. cp.async double-buffered.
// ---------------------------------------------------------------------------
__global__ __launch_bounds__(256, 2) void k3_gemm_A()
{
    extern __shared__ __nv_bfloat16 dyn[];
    const int p = blockIdx.x;
    const int b = blockIdx.y;
    const int tid = threadIdx.x;
    const int warp = tid >> 5, lane = tid & 31;
    const int wm = warp >> 2, wn = warp & 3;

    unsigned sb = (unsigned)__cvta_generic_to_shared(dyn);

    const size_t base = (size_t)b * T_ * H_ + p * 128;
    const __nv_bfloat16* Ah = &g_keyh[base];
    const __nv_bfloat16* Al = &g_keyl[base];
    const __nv_bfloat16* Bh = &g_ktrh[base];
    const __nv_bfloat16* Bl = &g_ktrl[base];

    float acc[4][4][4];
#pragma unroll
    for (int i = 0; i < 4; i++)
#pragma unroll
        for (int j = 0; j < 4; j++)
#pragma unroll
            for (int r = 0; r < 4; r++) acc[i][j][r] = 0.f;

#define NK3 4
    {
        unsigned s0 = sb;
        cpa_rm(s0, Ah, s0 + RM_BUF_HALVES * 2u, Al, H_, tid);
        cpa_rm(s0 + RM_BUF_HALVES * 4u, Bh, s0 + RM_BUF_HALVES * 6u, Bl, H_, tid);
        CP_COMMIT();
    }
    for (int k = 0; k < NK3; k++) {
        CP_WAIT0();
        __syncthreads();
        if (k + 1 < NK3) {
            unsigned s1 = sb + (unsigned)(((k + 1) & 1) * RM_STAGE_HALVES) * 2u;
            cpa_rm(s1, Ah + (k + 1) * 32, s1 + RM_BUF_HALVES * 2u, Al + (k + 1) * 32, H_, tid);
            cpa_rm(s1 + RM_BUF_HALVES * 4u, Bh + (k + 1) * 32,
                   s1 + RM_BUF_HALVES * 6u, Bl + (k + 1) * 32, H_, tid);
            CP_COMMIT();
        }
        unsigned s = sb + (unsigned)((k & 1) * RM_STAGE_HALVES) * 2u;
        mma_step_rm(s, s + RM_BUF_HALVES * 2u, s + RM_BUF_HALVES * 4u,
                    s + RM_BUF_HALVES * 6u, wm, wn, lane, acc);
    }
    epilogue(&g_Apart[(size_t)(p * B_ + b) * (T_ * T_)], T_, 1.f, wm, wn, lane, acc);
}

// ---------------------------------------------------------------------------
// K4: value-side scan, warp-autonomous (R5). Writes vals (f32) + vtr hi/lo bf16.
// ---------------------------------------------------------------------------
#define K4_BLK 16

__global__ __launch_bounds__(512) void k4_scan_val(float* __restrict__ out)
{
    extern __shared__ float sm4[];
    float* A_s   = sm4;            // [t][s] 128*128
    float* vtr_s = sm4 + 16384;    // [s][lh] 128*256

    const int b    = blockIdx.x / 3;
    const int hb   = blockIdx.x % 3;
    const int tid  = threadIdx.x;
    const int warp = tid >> 5;
    const int lane = tid & 31;
    const int lr   = lane & 15;
    const int half = lane >> 4;
    const int lh   = warp * 16 + lr;
    const int h    = hb * 256 + lh;

    {
        const float* ap = &g_Apart[(size_t)b * (T_ * T_)];
        for (int e = tid * 4; e < T_ * T_; e += 512 * 4) {
            float4 s = *(const float4*)&ap[e];
#pragma unroll
            for (int p = 1; p < 6; p++) {
                float4 v = *(const float4*)&ap[(size_t)p * B_ * T_ * T_ + e];
                s.x += v.x; s.y += v.y; s.z += v.z; s.w += v.w;
            }
            *(float4*)&A_s[e] = s;
        }
    }
    __syncthreads();

    const float* ivp = &g_i[b * T_ * H2_ + H_ + h];
    const int gbase = (b * T_) * H_ + h;
    float* valso = &out[OUT_VALS_ + gbase];

    float vv = 0.f, vtr = 0.f;

    for (int t0 = 0; t0 < T_; t0 += K4_BLK) {
        float iv_blk[K4_BLK];
#pragma unroll
        for (int j = 0; j < K4_BLK; j++) iv_blk[j] = ivp[(t0 + j) * H2_];

        const int mid  = t0 >> 1;
        const int sbeg = half ? mid : 0;
        const int send = half ? t0  : mid;

        float acc[K4_BLK];
#pragma unroll
        for (int j = 0; j < K4_BLK; j++) acc[j] = 0.f;

        for (int s4 = sbeg; s4 < send; s4 += 4) {
            float v0 = vtr_s[(s4 + 0) * 256 + lh];
            float v1 = vtr_s[(s4 + 1) * 256 + lh];
            float v2 = vtr_s[(s4 + 2) * 256 + lh];
            float v3 = vtr_s[(s4 + 3) * 256 + lh];
#pragma unroll
            for (int j = 0; j < K4_BLK; j++) {
                float4 a = *(const float4*)&A_s[(t0 + j) * T_ + s4];
                acc[j] = fmaf(a.x, v0, acc[j]);
                acc[j] = fmaf(a.y, v1, acc[j]);
                acc[j] = fmaf(a.z, v2, acc[j]);
                acc[j] = fmaf(a.w, v3, acc[j]);
            }
        }
#pragma unroll
        for (int j = 0; j < K4_BLK; j++)
            acc[j] += __shfl_xor_sync(0xFFFFFFFFu, acc[j], 16);

        float vtr_blk[K4_BLK];
#pragma unroll
        for (int j = 0; j < K4_BLK; j++) {
            const int t = t0 + j;
            float a = acc[j];
            const float* Arow = &A_s[t * T_ + t0];
#pragma unroll
            for (int sj = 0; sj < j; sj++)
                a = fmaf(Arow[sj], vtr_blk[sj], a);
            float ikv = CIKV_ * a;

            vv = ALPHA_ * vv + OMA_ * (iv_blk[j] + ikv);
            float val = tanh_fast(vv);
            vtr = DTR_ * vtr + OMD_ * val;
            vtr_blk[j] = vtr;
            if (!half) {
                valso[t * H_] = val;
                vtr_s[t * 256 + lh] = vtr;
                __nv_bfloat16 hh, ll;
                split_bf16(vtr, hh, ll);
                g_vtrh[gbase + t * H_] = hh;
                g_vtrl[gbase + t * H_] = ll;
            }
        }
        __syncwarp();
    }
}

// ---------------------------------------------------------------------------
// K5: mem[b][i][j] = eta * sum_s vtr[b,s,i]*ktr[b,s,j]
//     k-major bf16 operands, trans-ldmatrix, cp.async double-buffered.
//     grid (6,6,32), NK=4. Dyn smem 2*34816 = 69632B.
// ---------------------------------------------------------------------------
__global__ __launch_bounds__(256, 2) void k5_gemm_mem(float* __restrict__ out)
{
    extern __shared__ __nv_bfloat16 dyn[];
    const int b  = blockIdx.z;
    const int i0 = blockIdx.y * 128;
    const int j0 = blockIdx.x * 128;
    const int tid = threadIdx.x;
    const int warp = tid >> 5, lane = tid & 31;
    const int wm = warp >> 2, wn = warp & 3;

    unsigned sb = (unsigned)__cvta_generic_to_shared(dyn);

    const size_t bb = (size_t)b * T_ * H_;
    const __nv_bfloat16* Ah = &g_vtrh[bb + i0];
    const __nv_bfloat16* Al = &g_vtrl[bb + i0];
    const __nv_bfloat16* Bh = &g_ktrh[bb + j0];
    const __nv_bfloat16* Bl = &g_ktrl[bb + j0];

    float acc[4][4][4];
#pragma unroll
    for (int i = 0; i < 4; i++)
#pragma unroll
        for (int j = 0; j < 4; j++)
#pragma unroll
            for (int r = 0; r < 4; r++) acc[i][j][r] = 0.f;

#define NK5 4
    {
        unsigned s0 = sb;
        cpa_km(s0, Ah, s0 + KM_BUF_HALVES * 2u, Al, H_, tid);
        cpa_km(s0 + KM_BUF_HALVES * 4u, Bh, s0 + KM_BUF_HALVES * 6u, Bl, H_, tid);
        CP_COMMIT();
    }
    for (int k = 0; k < NK5; k++) {
        CP_WAIT0();
        __syncthreads();
        if (k + 1 < NK5) {
            unsigned s1 = sb + (unsigned)(((k + 1) & 1) * KM_STAGE_HALVES) * 2u;
            const size_t so = (size_t)(k + 1) * 32 * H_;
            cpa_km(s1, Ah + so, s1 + KM_BUF_HALVES * 2u, Al + so, H_, tid);
            cpa_km(s1 + KM_BUF_HALVES * 4u, Bh + so,
                   s1 + KM_BUF_HALVES * 6u, Bl + so, H_, tid);
            CP_COMMIT();
        }
        unsigned s = sb + (unsigned)((k & 1) * KM_STAGE_HALVES) * 2u;
        mma_step_km(s, s + KM_BUF_HALVES * 2u, s + KM_BUF_HALVES * 4u,
                    s + KM_BUF_HALVES * 6u, wm, wn, lane, acc);
    }
    epilogue(&out[(size_t)b * (H_ * H_) + (size_t)i0 * H_ + j0], H_, ETA_,
             wm, wn, lane, acc);
}

// ---------------------------------------------------------------------------
extern "C" void kernel_launch(void* const* d_in, const int* in_sizes, int n_in,
                              void* d_out, int out_size)
{
    const float* x = (const float*)d_in[0];   // (32,128,256)
    const float* W = (const float*)d_in[1];   // (1536,256)
    float* out = (float*)d_out;               // mem | keys | vals

    const int smem_rm = 2 * RM_STAGE_HALVES * 2;  // 81920
    const int smem_km = 2 * KM_STAGE_HALVES * 2;  // 69632
    const int smem_k4 = (16384 + 32768) * 4;      // 196608

    (void)cudaFuncSetAttribute(k1_gemm_in,
        cudaFuncAttributeMaxDynamicSharedMemorySize, smem_rm);
    (void)cudaFuncSetAttribute(k3_gemm_A,
        cudaFuncAttributeMaxDynamicSharedMemorySize, smem_rm);
    (void)cudaFuncSetAttribute(k5_gemm_mem,
        cudaFuncAttributeMaxDynamicSharedMemorySize, smem_km);
    (void)cudaFuncSetAttribute(k4_scan_val,
        cudaFuncAttributeMaxDynamicSharedMemorySize, smem_k4);

    k0_convert<<<(XN_ + WN_ + 1023) / 1024, 256>>>(x, W);
    k1_gemm_in<<<dim3(12, 32), 256, smem_rm>>>();
    k2_scan_key<<<96, 256>>>(out);
    k3_gemm_A<<<dim3(6, 32), 256, smem_rm>>>();
    k4_scan_val<<<96, 512, smem_k4>>>(out);
    k5_gemm_mem<<<dim3(6, 6, 32), 256, smem_km>>>(out);
}